// round 1
// baseline (speedup 1.0000x reference)
#include <cuda_runtime.h>

#define BB 64
#define CC 512
#define HH 28
#define WW 28
#define HWSZ (HH*WW)
#define HID 32
#define NPLANE (BB*CC)
#define NLAYERS 4

// Scratch (static device memory -- allocation-free)
__device__ float g_buf[(size_t)NPLANE * HWSZ];   // ping-pong x buffer (~103MB)
__device__ float g_seq[NPLANE];                  // pooled means [B,C]
__device__ float g_ht[NPLANE];                   // LSTM hidden
__device__ float g_ct[NPLANE];                   // LSTM cell
__device__ float g_hid[2 * BB * HID];            // bottleneck activations: [path(i/h)][b][k]
__device__ float g_gi[BB * 3 * CC];              // input-path gates (reused by 2nd cell)
__device__ float g_gh2[3 * CC];                  // 2nd cell hidden-path gates (row 0)

__device__ __forceinline__ float sigmf(float x) { return 1.0f / (1.0f + __expf(-x)); }

__device__ __forceinline__ float blockReduceSum(float v) {
    __shared__ float red[32];
    int lane = threadIdx.x & 31, w = threadIdx.x >> 5;
    #pragma unroll
    for (int o = 16; o; o >>= 1) v += __shfl_down_sync(0xffffffffu, v, o);
    if (lane == 0) red[w] = v;
    __syncthreads();
    int nw = blockDim.x >> 5;
    v = (threadIdx.x < nw) ? red[threadIdx.x] : 0.f;
    if (w == 0) {
        #pragma unroll
        for (int o = 16; o; o >>= 1) v += __shfl_down_sync(0xffffffffu, v, o);
    }
    return v;
}

// Initial pool of input x + zero LSTM state. One block per (b,c) plane.
__global__ void k_pool_init(const float* __restrict__ x) {
    int plane = blockIdx.x;
    const float* p = x + (size_t)plane * HWSZ;
    float s = 0.f;
    for (int i = threadIdx.x; i < HWSZ; i += blockDim.x) s += p[i];
    s = blockReduceSum(s);
    if (threadIdx.x == 0) {
        g_seq[plane] = s * (1.0f / HWSZ);
        g_ht[plane] = 0.f;
        g_ct[plane] = 0.f;
    }
}

// Bottleneck layer 1 for both paths: hid = relu(inp @ W1^T + b1).
// One warp per output element (2 paths * 64 b * 32 k = 4096 warps).
__global__ void k_mlp1(const float* __restrict__ w_ih_l1, const float* __restrict__ b_ih_l1,
                       const float* __restrict__ w_hh_l1, const float* __restrict__ b_hh_l1) {
    int gw = (blockIdx.x * blockDim.x + threadIdx.x) >> 5;
    int lane = threadIdx.x & 31;
    if (gw >= 2 * BB * HID) return;
    int path = gw / (BB * HID);
    int rem  = gw % (BB * HID);
    int b = rem / HID, k = rem % HID;
    const float* inp = (path ? g_ht : g_seq) + b * CC;
    const float* wr  = (path ? w_hh_l1 : w_ih_l1) + k * CC;
    float s = 0.f;
    for (int j = lane; j < CC; j += 32) s += inp[j] * wr[j];
    #pragma unroll
    for (int o = 16; o; o >>= 1) s += __shfl_down_sync(0xffffffffu, s, o);
    if (lane == 0) {
        float bias = (path ? b_hh_l1 : b_ih_l1)[k];
        g_hid[path * BB * HID + b * HID + k] = fmaxf(s + bias, 0.f);
    }
}

// Layer-2 projection (32 -> 3C) for both paths + LSTM gate update.
// One thread per (b,c). Stores input-path gates for reuse by the second cell.
__global__ void k_gate(const float* __restrict__ w_ih_l2, const float* __restrict__ b_ih_l2,
                       const float* __restrict__ w_hh_l2, const float* __restrict__ b_hh_l2) {
    int idx = blockIdx.x * blockDim.x + threadIdx.x;
    if (idx >= NPLANE) return;
    int b = idx / CC, c = idx % CC;
    const float* hi = g_hid + b * HID;
    const float* hh = g_hid + BB * HID + b * HID;
    float gi[3], gh[3];
    #pragma unroll
    for (int g = 0; g < 3; g++) { gi[g] = b_ih_l2[g * CC + c]; gh[g] = b_hh_l2[g * CC + c]; }
    #pragma unroll
    for (int k = 0; k < HID; k++) {
        float a = hi[k], h = hh[k];
        #pragma unroll
        for (int g = 0; g < 3; g++) {
            gi[g] += a * w_ih_l2[(g * CC + c) * HID + k];
            gh[g] += h * w_hh_l2[(g * CC + c) * HID + k];
        }
    }
    #pragma unroll
    for (int g = 0; g < 3; g++) g_gi[(b * 3 + g) * CC + c] = gi[g];
    float ig = sigmf(gi[0] + gh[0]);
    float fg = sigmf(gi[1] + gh[1]);
    float cg = tanhf(gi[2] + gh[2]);
    float nc = fg * g_ct[idx] + ig * cg;
    g_ct[idx] = nc;
    g_ht[idx] = sigmf(nc);
}

// Second cell's hidden path with hx = ht[0] (single row). One block.
__global__ void k_row0(const float* __restrict__ w_hh_l1, const float* __restrict__ b_hh_l1,
                       const float* __restrict__ w_hh_l2, const float* __restrict__ b_hh_l2) {
    __shared__ float hid2[HID];
    int tid = threadIdx.x, lane = tid & 31, w = tid >> 5;  // 16 warps
    for (int k = w; k < HID; k += 16) {
        float s = 0.f;
        const float* wr = w_hh_l1 + k * CC;
        for (int j = lane; j < CC; j += 32) s += g_ht[j] * wr[j];
        #pragma unroll
        for (int o = 16; o; o >>= 1) s += __shfl_down_sync(0xffffffffu, s, o);
        if (lane == 0) hid2[k] = fmaxf(s + b_hh_l1[k], 0.f);
    }
    __syncthreads();
    for (int j = tid; j < 3 * CC; j += blockDim.x) {
        float acc = b_hh_l2[j];
        #pragma unroll
        for (int k = 0; k < HID; k++) acc += hid2[k] * w_hh_l2[j * HID + k];
        g_gh2[j] = acc;
    }
}

// Fused update: x_new = x*(1+out_h) + dwconv3x3(x); also plane-mean for next layer.
// One block per (b,c) plane.
__global__ void k_update(const float* __restrict__ xin, float* __restrict__ xout,
                         const float* __restrict__ dw, int writeSeq) {
    int plane = blockIdx.x;
    int b = plane / CC, c = plane % CC;
    __shared__ float tile[30][30];
    __shared__ float sScale;

    if (threadIdx.x == 0) {
        // second cell gate math: g = g_i(seq) + g_h2(ht[0]); cx = ct[0][c]
        float i2 = g_gi[(b * 3 + 0) * CC + c] + g_gh2[c];
        float f2 = g_gi[(b * 3 + 1) * CC + c] + g_gh2[CC + c];
        float c2 = g_gi[(b * 3 + 2) * CC + c] + g_gh2[2 * CC + c];
        float nc2 = sigmf(f2) * g_ct[c] + sigmf(i2) * tanhf(c2);
        sScale = 1.0f + sigmf(nc2);
    }

    const float* p = xin + (size_t)plane * HWSZ;
    for (int i = threadIdx.x; i < 30 * 30; i += blockDim.x) {
        int y = i / 30, x = i % 30;
        int yy = y - 1, xx = x - 1;
        float v = 0.f;
        if (yy >= 0 && yy < HH && xx >= 0 && xx < WW) v = p[yy * WW + xx];
        tile[y][x] = v;
    }
    float wq[9];
    const float* wp = dw + c * 9;
    #pragma unroll
    for (int q = 0; q < 9; q++) wq[q] = wp[q];
    __syncthreads();

    float scale = sScale;
    float sum = 0.f;
    float* q = xout + (size_t)plane * HWSZ;
    for (int i = threadIdx.x; i < HWSZ; i += blockDim.x) {
        int y = i / WW, x = i % WW;
        float conv =
            wq[0] * tile[y][x]     + wq[1] * tile[y][x + 1]     + wq[2] * tile[y][x + 2] +
            wq[3] * tile[y + 1][x] + wq[4] * tile[y + 1][x + 1] + wq[5] * tile[y + 1][x + 2] +
            wq[6] * tile[y + 2][x] + wq[7] * tile[y + 2][x + 1] + wq[8] * tile[y + 2][x + 2];
        float o = tile[y + 1][x + 1] * scale + conv;
        q[i] = o;
        sum += o;
    }
    if (writeSeq) {
        sum = blockReduceSum(sum);
        if (threadIdx.x == 0) g_seq[plane] = sum * (1.0f / HWSZ);
    }
}

extern "C" void kernel_launch(void* const* d_in, const int* in_sizes, int n_in,
                              void* d_out, int out_size) {
    const float* x        = (const float*)d_in[0];
    const float* w_ih_l1  = (const float*)d_in[1];
    const float* b_ih_l1  = (const float*)d_in[2];
    const float* w_ih_l2  = (const float*)d_in[3];
    const float* b_ih_l2  = (const float*)d_in[4];
    const float* w_hh_l1  = (const float*)d_in[5];
    const float* b_hh_l1  = (const float*)d_in[6];
    const float* w_hh_l2  = (const float*)d_in[7];
    const float* b_hh_l2  = (const float*)d_in[8];
    const float* dw       = (const float*)d_in[9];
    float* out = (float*)d_out;

    float* buf = nullptr;
    cudaGetSymbolAddress((void**)&buf, g_buf);

    k_pool_init<<<NPLANE, 256>>>(x);

    const float* cur = x;
    for (int l = 0; l < NLAYERS; l++) {
        k_mlp1<<<512, 256>>>(w_ih_l1, b_ih_l1, w_hh_l1, b_hh_l1);
        k_gate<<<NPLANE / 256, 256>>>(w_ih_l2, b_ih_l2, w_hh_l2, b_hh_l2);
        k_row0<<<1, 512>>>(w_hh_l1, b_hh_l1, w_hh_l2, b_hh_l2);
        float* nxt = ((l & 1) == 0) ? buf : out;   // l0->buf, l1->out, l2->buf, l3->out
        k_update<<<NPLANE, 256>>>(cur, nxt, dw, (l < NLAYERS - 1) ? 1 : 0);
        cur = nxt;
    }
}

// round 2
// speedup vs baseline: 1.2371x; 1.2371x over previous
#include <cuda_runtime.h>

#define BB 64
#define CC 512
#define HH 28
#define WW 28
#define HWSZ (HH*WW)
#define HID 32
#define NPLANE (BB*CC)
#define NLAYERS 4

// Scratch (static device memory -- allocation-free)
__device__ float g_buf[(size_t)NPLANE * HWSZ];   // ping-pong x buffer (~103MB)
__device__ float g_seq[NPLANE];                  // pooled means [B,C]
__device__ float g_ht[NPLANE];                   // LSTM hidden
__device__ float g_ct[NPLANE];                   // LSTM cell
__device__ float g_gi[BB * 3 * CC];              // input-path gates (reused by 2nd cell)
__device__ float g_gh2[3 * CC];                  // 2nd cell hidden-path gates (row 0)
__device__ int   g_cnt = 0;                      // last-block counter (self-resetting)

__device__ __forceinline__ float sigmf(float x) { return 1.0f / (1.0f + __expf(-x)); }

__device__ __forceinline__ float blockReduceSum(float v) {
    __shared__ float red[32];
    int lane = threadIdx.x & 31, w = threadIdx.x >> 5;
    #pragma unroll
    for (int o = 16; o; o >>= 1) v += __shfl_down_sync(0xffffffffu, v, o);
    if (lane == 0) red[w] = v;
    __syncthreads();
    int nw = blockDim.x >> 5;
    v = (threadIdx.x < nw) ? red[threadIdx.x] : 0.f;
    if (w == 0) {
        #pragma unroll
        for (int o = 16; o; o >>= 1) v += __shfl_down_sync(0xffffffffu, v, o);
    }
    return v;
}

// Initial pool of input x + zero LSTM state. One block per (b,c) plane. float4 loads.
__global__ void k_pool_init(const float* __restrict__ x) {
    int plane = blockIdx.x, tid = threadIdx.x;
    float s = 0.f;
    if (tid < 196) {
        float4 v = ((const float4*)(x + (size_t)plane * HWSZ))[tid];
        s = v.x + v.y + v.z + v.w;
    }
    s = blockReduceSum(s);
    if (tid == 0) {
        g_seq[plane] = s * (1.0f / HWSZ);
        g_ht[plane] = 0.f;
        g_ct[plane] = 0.f;
        if (plane == 0) g_cnt = 0;   // belt & braces (counter self-resets too)
    }
}

// Fused cell: bottleneck GEMVs (both paths) + gate update for one batch b per block.
// Last block additionally computes the second cell's hidden path (ht[0] -> g_gh2).
__global__ void __launch_bounds__(512) k_cell(
        const float* __restrict__ w_ih_l1, const float* __restrict__ b_ih_l1,
        const float* __restrict__ w_ih_l2, const float* __restrict__ b_ih_l2,
        const float* __restrict__ w_hh_l1, const float* __restrict__ b_hh_l1,
        const float* __restrict__ w_hh_l2, const float* __restrict__ b_hh_l2) {
    __shared__ float sin0[CC], sin1[CC];
    __shared__ float hi[HID], hh[HID];
    __shared__ int sLast;
    int b = blockIdx.x, tid = threadIdx.x, lane = tid & 31, w = tid >> 5;  // 16 warps

    sin0[tid] = g_seq[b * CC + tid];
    sin1[tid] = g_ht[b * CC + tid];
    __syncthreads();

    // Phase 1: 64 dots of length 512 (2 paths x 32 hidden). Warp w does d = w + 16t.
    #pragma unroll
    for (int t = 0; t < 4; t++) {
        int d = w + 16 * t;
        int path = d >> 5, k = d & 31;
        const float* wr = (path ? w_hh_l1 : w_ih_l1) + k * CC;
        const float* in = path ? sin1 : sin0;
        float s = 0.f;
        #pragma unroll
        for (int j = lane; j < CC; j += 32) s += in[j] * wr[j];
        #pragma unroll
        for (int o = 16; o; o >>= 1) s += __shfl_down_sync(0xffffffffu, s, o);
        if (lane == 0) {
            float v = fmaxf(s + (path ? b_hh_l1 : b_ih_l1)[k], 0.f);
            if (path) hh[k] = v; else hi[k] = v;
        }
    }
    __syncthreads();

    // Phase 2: per-channel gate update (c = tid).
    int c = tid;
    float gi[3], gh[3];
    #pragma unroll
    for (int g = 0; g < 3; g++) { gi[g] = b_ih_l2[g * CC + c]; gh[g] = b_hh_l2[g * CC + c]; }
    #pragma unroll
    for (int k = 0; k < HID; k++) {
        float a = hi[k], h = hh[k];
        #pragma unroll
        for (int g = 0; g < 3; g++) {
            gi[g] += a * w_ih_l2[(g * CC + c) * HID + k];
            gh[g] += h * w_hh_l2[(g * CC + c) * HID + k];
        }
    }
    #pragma unroll
    for (int g = 0; g < 3; g++) g_gi[(b * 3 + g) * CC + c] = gi[g];
    float ig = sigmf(gi[0] + gh[0]);
    float fg = sigmf(gi[1] + gh[1]);
    float cg = tanhf(gi[2] + gh[2]);
    float nc = fg * g_ct[b * CC + c] + ig * cg;
    g_ct[b * CC + c] = nc;
    g_ht[b * CC + c] = sigmf(nc);

    // Last-block tail: second cell's hidden path with hx = ht[0].
    __threadfence();
    __syncthreads();
    if (tid == 0) {
        int old = atomicAdd(&g_cnt, 1);
        sLast = (old == (int)gridDim.x - 1);
        if (sLast) g_cnt = 0;   // reset for next use (exclusive owner)
    }
    __syncthreads();
    if (sLast) {
        sin0[tid] = g_ht[tid];   // ht[0][:]
        __syncthreads();
        #pragma unroll
        for (int t = 0; t < 2; t++) {
            int k = w + 16 * t;
            const float* wr = w_hh_l1 + k * CC;
            float s = 0.f;
            #pragma unroll
            for (int j = lane; j < CC; j += 32) s += sin0[j] * wr[j];
            #pragma unroll
            for (int o = 16; o; o >>= 1) s += __shfl_down_sync(0xffffffffu, s, o);
            if (lane == 0) hi[k] = fmaxf(s + b_hh_l1[k], 0.f);
        }
        __syncthreads();
        #pragma unroll
        for (int j = tid; j < 3 * CC; j += 512) {
            float acc = b_hh_l2[j];
            #pragma unroll
            for (int k = 0; k < HID; k++) acc += hi[k] * w_hh_l2[j * HID + k];
            g_gh2[j] = acc;
        }
    }
}

// Fused update: x_new = x*(1+out_h) + dwconv3x3(x); plane-mean for next layer.
// One block (256 thr) per (b,c) plane; float4 I/O, bounds-checked smem conv.
__global__ void __launch_bounds__(256) k_update(
        const float* __restrict__ xin, float* __restrict__ xout,
        const float* __restrict__ dw, int writeSeq) {
    int plane = blockIdx.x;
    int b = plane >> 9, c = plane & 511;
    __shared__ float s[HWSZ];
    __shared__ float sScale;
    int tid = threadIdx.x;

    if (tid == 0) {
        float i2 = g_gi[(b * 3 + 0) * CC + c] + g_gh2[c];
        float f2 = g_gi[(b * 3 + 1) * CC + c] + g_gh2[CC + c];
        float c2 = g_gi[(b * 3 + 2) * CC + c] + g_gh2[2 * CC + c];
        float nc2 = sigmf(f2) * g_ct[c] + sigmf(i2) * tanhf(c2);
        sScale = 1.0f + sigmf(nc2);
    }
    if (tid < 196) {
        ((float4*)s)[tid] = ((const float4*)(xin + (size_t)plane * HWSZ))[tid];
    }
    float wq[9];
    const float* wp = dw + c * 9;
    #pragma unroll
    for (int q = 0; q < 9; q++) wq[q] = wp[q];
    __syncthreads();

    float scale = sScale;
    float sum = 0.f;
    if (tid < 196) {
        float o[4];
        int base = tid * 4;
        #pragma unroll
        for (int u = 0; u < 4; u++) {
            int p = base + u;
            int y = p / WW, x = p - y * WW;
            float conv = 0.f;
            #pragma unroll
            for (int dy = -1; dy <= 1; dy++) {
                int yy = y + dy;
                if (yy < 0 || yy >= HH) continue;
                #pragma unroll
                for (int dx = -1; dx <= 1; dx++) {
                    int xx = x + dx;
                    if (xx < 0 || xx >= WW) continue;
                    conv += wq[(dy + 1) * 3 + (dx + 1)] * s[yy * WW + xx];
                }
            }
            o[u] = s[p] * scale + conv;
            sum += o[u];
        }
        float4 ov = make_float4(o[0], o[1], o[2], o[3]);
        ((float4*)(xout + (size_t)plane * HWSZ))[tid] = ov;
    }
    if (writeSeq) {
        sum = blockReduceSum(sum);
        if (tid == 0) g_seq[plane] = sum * (1.0f / HWSZ);
    }
}

extern "C" void kernel_launch(void* const* d_in, const int* in_sizes, int n_in,
                              void* d_out, int out_size) {
    const float* x        = (const float*)d_in[0];
    const float* w_ih_l1  = (const float*)d_in[1];
    const float* b_ih_l1  = (const float*)d_in[2];
    const float* w_ih_l2  = (const float*)d_in[3];
    const float* b_ih_l2  = (const float*)d_in[4];
    const float* w_hh_l1  = (const float*)d_in[5];
    const float* b_hh_l1  = (const float*)d_in[6];
    const float* w_hh_l2  = (const float*)d_in[7];
    const float* b_hh_l2  = (const float*)d_in[8];
    const float* dw       = (const float*)d_in[9];
    float* out = (float*)d_out;

    float* buf = nullptr;
    cudaGetSymbolAddress((void**)&buf, g_buf);

    k_pool_init<<<NPLANE, 256>>>(x);

    const float* cur = x;
    for (int l = 0; l < NLAYERS; l++) {
        k_cell<<<BB, 512>>>(w_ih_l1, b_ih_l1, w_ih_l2, b_ih_l2,
                            w_hh_l1, b_hh_l1, w_hh_l2, b_hh_l2);
        float* nxt = ((l & 1) == 0) ? buf : out;   // l0->buf, l1->out, l2->buf, l3->out
        k_update<<<NPLANE, 256>>>(cur, nxt, dw, (l < NLAYERS - 1) ? 1 : 0);
        cur = nxt;
    }
}

// round 3
// speedup vs baseline: 1.6442x; 1.3291x over previous
#include <cuda_runtime.h>

#define BB 64
#define CC 512
#define HH 28
#define WW 28
#define HWSZ (HH*WW)
#define HID 32
#define NPLANE (BB*CC)
#define NLAYERS 4

// Scratch (static device memory -- allocation-free)
__device__ float g_buf[(size_t)NPLANE * HWSZ];   // ping-pong x buffer (~103MB)
__device__ float g_seq[NPLANE];                  // pooled means [B,C]
__device__ float g_ht[NPLANE];                   // LSTM hidden
__device__ float g_ct[NPLANE];                   // LSTM cell
__device__ float g_gi[BB * 3 * CC];              // input-path gates (reused by 2nd cell)
__device__ float g_gh2[3 * CC];                  // 2nd cell hidden-path gates (row 0)

__device__ __forceinline__ float sigmf(float x) { return 1.0f / (1.0f + __expf(-x)); }

__device__ __forceinline__ float blockReduceSum(float v) {
    __shared__ float red[32];
    int lane = threadIdx.x & 31, w = threadIdx.x >> 5;
    #pragma unroll
    for (int o = 16; o; o >>= 1) v += __shfl_down_sync(0xffffffffu, v, o);
    if (lane == 0) red[w] = v;
    __syncthreads();
    int nw = (blockDim.x + 31) >> 5;
    v = (threadIdx.x < nw) ? red[threadIdx.x] : 0.f;
    if (w == 0) {
        #pragma unroll
        for (int o = 16; o; o >>= 1) v += __shfl_down_sync(0xffffffffu, v, o);
    }
    return v;
}

// Initial pool of input x + zero LSTM state. One block per (b,c) plane. float4 loads.
__global__ void __launch_bounds__(224) k_pool_init(const float* __restrict__ x) {
    int plane = blockIdx.x, tid = threadIdx.x;
    float s = 0.f;
    if (tid < 196) {
        float4 v = ((const float4*)(x + (size_t)plane * HWSZ))[tid];
        s = v.x + v.y + v.z + v.w;
    }
    s = blockReduceSum(s);
    if (tid == 0) {
        g_seq[plane] = s * (1.0f / HWSZ);
        g_ht[plane] = 0.f;
        g_ct[plane] = 0.f;
    }
}

// Fused cell: bottleneck GEMVs (both paths) + gate update for one batch b per block.
// Block 0 additionally computes the second cell's hidden path (ht[0] -> g_gh2)
// immediately after its own gate update -- ht[0] depends only on block 0's work,
// so no grid-wide synchronization is needed.
__global__ void __launch_bounds__(512) k_cell(
        const float* __restrict__ w_ih_l1, const float* __restrict__ b_ih_l1,
        const float* __restrict__ w_ih_l2, const float* __restrict__ b_ih_l2,
        const float* __restrict__ w_hh_l1, const float* __restrict__ b_hh_l1,
        const float* __restrict__ w_hh_l2, const float* __restrict__ b_hh_l2) {
    __shared__ float sin0[CC], sin1[CC];
    __shared__ float hi[HID], hh[HID];
    int b = blockIdx.x, tid = threadIdx.x, lane = tid & 31, w = tid >> 5;  // 16 warps

    sin0[tid] = g_seq[b * CC + tid];
    sin1[tid] = g_ht[b * CC + tid];
    __syncthreads();

    // Phase 1: 64 dots of length 512 (2 paths x 32 hidden). Warp w does d = w + 16t.
    #pragma unroll
    for (int t = 0; t < 4; t++) {
        int d = w + 16 * t;
        int path = d >> 5, k = d & 31;
        const float* wr = (path ? w_hh_l1 : w_ih_l1) + k * CC;
        const float* in = path ? sin1 : sin0;
        float s = 0.f;
        #pragma unroll
        for (int j = lane; j < CC; j += 32) s += in[j] * wr[j];
        #pragma unroll
        for (int o = 16; o; o >>= 1) s += __shfl_down_sync(0xffffffffu, s, o);
        if (lane == 0) {
            float v = fmaxf(s + (path ? b_hh_l1 : b_ih_l1)[k], 0.f);
            if (path) hh[k] = v; else hi[k] = v;
        }
    }
    __syncthreads();

    // Phase 2: per-channel gate update (c = tid). float4 weight loads (8 per gate).
    int c = tid;
    float gi[3], gh[3];
    #pragma unroll
    for (int g = 0; g < 3; g++) { gi[g] = b_ih_l2[g * CC + c]; gh[g] = b_hh_l2[g * CC + c]; }
    #pragma unroll
    for (int g = 0; g < 3; g++) {
        const float4* wi4 = (const float4*)&w_ih_l2[(g * CC + c) * HID];
        const float4* wh4 = (const float4*)&w_hh_l2[(g * CC + c) * HID];
        #pragma unroll
        for (int q = 0; q < 8; q++) {
            float4 wi = wi4[q], wh = wh4[q];
            int k = q * 4;
            gi[g] += hi[k] * wi.x + hi[k+1] * wi.y + hi[k+2] * wi.z + hi[k+3] * wi.w;
            gh[g] += hh[k] * wh.x + hh[k+1] * wh.y + hh[k+2] * wh.z + hh[k+3] * wh.w;
        }
    }
    #pragma unroll
    for (int g = 0; g < 3; g++) g_gi[(b * 3 + g) * CC + c] = gi[g];
    float ig = sigmf(gi[0] + gh[0]);
    float fg = sigmf(gi[1] + gh[1]);
    float cg = tanhf(gi[2] + gh[2]);
    float nc = fg * g_ct[b * CC + c] + ig * cg;
    float nh = sigmf(nc);
    g_ct[b * CC + c] = nc;
    g_ht[b * CC + c] = nh;

    // Block-0 tail: second cell's hidden path with hx = ht[0] (our own fresh nh).
    if (b == 0) {
        sin0[c] = nh;           // ht[0][:], no global round-trip
        __syncthreads();
        #pragma unroll
        for (int t = 0; t < 2; t++) {
            int k = w + 16 * t;
            const float* wr = w_hh_l1 + k * CC;
            float s = 0.f;
            #pragma unroll
            for (int j = lane; j < CC; j += 32) s += sin0[j] * wr[j];
            #pragma unroll
            for (int o = 16; o; o >>= 1) s += __shfl_down_sync(0xffffffffu, s, o);
            if (lane == 0) hi[k] = fmaxf(s + b_hh_l1[k], 0.f);
        }
        __syncthreads();
        #pragma unroll
        for (int j = tid; j < 3 * CC; j += 512) {
            float acc = b_hh_l2[j];
            const float4* wh4 = (const float4*)&w_hh_l2[j * HID];
            #pragma unroll
            for (int q = 0; q < 8; q++) {
                float4 wh = wh4[q];
                int k = q * 4;
                acc += hi[k] * wh.x + hi[k+1] * wh.y + hi[k+2] * wh.z + hi[k+3] * wh.w;
            }
            g_gh2[j] = acc;
        }
    }
}

// Fused update: x_new = x*(1+out_h) + dwconv3x3(x); plane-mean for next layer.
// One block (224 thr) per (b,c) plane; float4 I/O, bounds-checked smem conv.
__global__ void __launch_bounds__(224) k_update(
        const float* __restrict__ xin, float* __restrict__ xout,
        const float* __restrict__ dw, int writeSeq) {
    int plane = blockIdx.x;
    int b = plane >> 9, c = plane & 511;
    __shared__ float s[HWSZ];
    __shared__ float sScale;
    int tid = threadIdx.x;

    if (tid == 0) {
        float i2 = g_gi[(b * 3 + 0) * CC + c] + g_gh2[c];
        float f2 = g_gi[(b * 3 + 1) * CC + c] + g_gh2[CC + c];
        float c2 = g_gi[(b * 3 + 2) * CC + c] + g_gh2[2 * CC + c];
        float nc2 = sigmf(f2) * g_ct[c] + sigmf(i2) * tanhf(c2);
        sScale = 1.0f + sigmf(nc2);
    }
    if (tid < 196) {
        ((float4*)s)[tid] = ((const float4*)(xin + (size_t)plane * HWSZ))[tid];
    }
    float wq[9];
    const float* wp = dw + c * 9;
    #pragma unroll
    for (int q = 0; q < 9; q++) wq[q] = wp[q];
    __syncthreads();

    float scale = sScale;
    float sum = 0.f;
    if (tid < 196) {
        float o[4];
        int base = tid * 4;
        #pragma unroll
        for (int u = 0; u < 4; u++) {
            int p = base + u;
            int y = p / WW, x = p - y * WW;
            float conv = 0.f;
            #pragma unroll
            for (int dy = -1; dy <= 1; dy++) {
                int yy = y + dy;
                if (yy < 0 || yy >= HH) continue;
                #pragma unroll
                for (int dx = -1; dx <= 1; dx++) {
                    int xx = x + dx;
                    if (xx < 0 || xx >= WW) continue;
                    conv += wq[(dy + 1) * 3 + (dx + 1)] * s[yy * WW + xx];
                }
            }
            o[u] = s[p] * scale + conv;
            sum += o[u];
        }
        float4 ov = make_float4(o[0], o[1], o[2], o[3]);
        ((float4*)(xout + (size_t)plane * HWSZ))[tid] = ov;
    }
    if (writeSeq) {
        sum = blockReduceSum(sum);
        if (tid == 0) g_seq[plane] = sum * (1.0f / HWSZ);
    }
}

extern "C" void kernel_launch(void* const* d_in, const int* in_sizes, int n_in,
                              void* d_out, int out_size) {
    const float* x        = (const float*)d_in[0];
    const float* w_ih_l1  = (const float*)d_in[1];
    const float* b_ih_l1  = (const float*)d_in[2];
    const float* w_ih_l2  = (const float*)d_in[3];
    const float* b_ih_l2  = (const float*)d_in[4];
    const float* w_hh_l1  = (const float*)d_in[5];
    const float* b_hh_l1  = (const float*)d_in[6];
    const float* w_hh_l2  = (const float*)d_in[7];
    const float* b_hh_l2  = (const float*)d_in[8];
    const float* dw       = (const float*)d_in[9];
    float* out = (float*)d_out;

    float* buf = nullptr;
    cudaGetSymbolAddress((void**)&buf, g_buf);

    k_pool_init<<<NPLANE, 224>>>(x);

    const float* cur = x;
    for (int l = 0; l < NLAYERS; l++) {
        k_cell<<<BB, 512>>>(w_ih_l1, b_ih_l1, w_ih_l2, b_ih_l2,
                            w_hh_l1, b_hh_l1, w_hh_l2, b_hh_l2);
        float* nxt = ((l & 1) == 0) ? buf : out;   // l0->buf, l1->out, l2->buf, l3->out
        k_update<<<NPLANE, 224>>>(cur, nxt, dw, (l < NLAYERS - 1) ? 1 : 0);
        cur = nxt;
    }
}